// round 12
// baseline (speedup 1.0000x reference)
#include <cuda_runtime.h>
#include <math.h>

#define LQ    512
#define KNN   64
#define DM    256
#define DP    128
#define DS    32
#define NL0   32
#define NRBF  36
#define MH    64
#define MOUT  38

// ---------------- scratch (static device arrays; no allocation) ----------------
__device__ float g_node_feat[LQ * NL0];
__device__ int   g_nbr[LQ * KNN];
__device__ float g_W2pad[MH * 48];
__device__ float g_b2pad[48];
__device__ float g_We1g[DP * 32];   // g_pair[c] * W_e1[c][j]
__device__ float g_S1[32];          // sum_c g_pair[c]*W_e1[c][j]
__device__ float g_S2[32];          // sum_c b_pair[c]*W_e1[c][j] + b_e1[j]
__device__ float g_m0p[LQ * 2 * 32];  // per-half m0 column sums
__device__ float g_o1p[LQ * 2 * 12];  // per-half out1 sums (9 used)

__device__ __forceinline__ float wsum(float v) {
#pragma unroll
    for (int o = 16; o; o >>= 1) v += __shfl_xor_sync(0xffffffffu, v, o);
    return v;
}
__device__ __forceinline__ void wsum2(float& a, float& b) {
#pragma unroll
    for (int o = 16; o; o >>= 1) {
        a += __shfl_xor_sync(0xffffffffu, a, o);
        b += __shfl_xor_sync(0xffffffffu, b, o);
    }
}

// ---- warp-register bitonic helpers (64 keys per warp, 2 per lane) ----
__device__ __forceinline__ unsigned long long shflx64(unsigned long long v, int m) {
    unsigned lo = __shfl_xor_sync(0xffffffffu, (unsigned)v, m);
    unsigned hi = __shfl_xor_sync(0xffffffffu, (unsigned)(v >> 32), m);
    return ((unsigned long long)hi << 32) | lo;
}
__device__ __forceinline__ void ce64(unsigned long long& r, int j, bool up, int lane) {
    unsigned long long p = shflx64(r, j);
    bool lower = ((lane & j) == 0);
    bool kmin = (lower == up);
    bool pless = (p < r);
    r = (kmin == pless) ? p : r;
}
// sort 64 keys (reg r0 holds element lane, r1 element lane+32), dir=true ascending
__device__ __forceinline__ void sort64(unsigned long long& r0, unsigned long long& r1,
                                       bool dir, int lane) {
#pragma unroll
    for (int k = 2; k <= 64; k <<= 1) {
#pragma unroll 6
        for (int j = k >> 1; j > 0; j >>= 1) {
            if (j == 32) {
                unsigned long long lo = (r0 < r1) ? r0 : r1;
                unsigned long long hi = (r0 < r1) ? r1 : r0;
                r0 = dir ? lo : hi; r1 = dir ? hi : lo;
            } else {
                bool up0, up1;
                if (k == 64)      { up0 = dir;  up1 = dir;  }
                else if (k == 32) { up0 = dir;  up1 = !dir; }
                else { bool u = (((lane & k) == 0) == dir); up0 = u; up1 = u; }
                ce64(r0, j, up0, lane);
                ce64(r1, j, up1, lane);
            }
        }
    }
}
// merge a bitonic 64-sequence into sorted order (direction dir)
__device__ __forceinline__ void merge64(unsigned long long& r0, unsigned long long& r1,
                                        bool dir, int lane) {
    {
        unsigned long long lo = (r0 < r1) ? r0 : r1;
        unsigned long long hi = (r0 < r1) ? r1 : r0;
        r0 = dir ? lo : hi; r1 = dir ? hi : lo;
    }
#pragma unroll
    for (int j = 16; j > 0; j >>= 1) {
        ce64(r0, j, dir, lane);
        ce64(r1, j, dir, lane);
    }
}

// ---------------- Kernel A: topk (0..511) + node features (512..575) + weight prep (576) ----------------
__global__ void __launch_bounds__(256) prep_kernel(
    const float* __restrict__ xyz,
    const float* __restrict__ msa, const float* __restrict__ seq1hot,
    const float* __restrict__ state,
    const float* __restrict__ g_msa, const float* __restrict__ b_msa,
    const float* __restrict__ g_state, const float* __restrict__ b_state,
    const float* __restrict__ W_x, const float* __restrict__ b_x,
    const float* __restrict__ g_node, const float* __restrict__ b_node,
    const float* __restrict__ W2, const float* __restrict__ b2,
    const float* __restrict__ g_pair, const float* __restrict__ b_pair,
    const float* __restrict__ W_e1, const float* __restrict__ b_e1)
{
    __shared__ __align__(16) float smem_f[3072];
    int tid = threadIdx.x;
    int w = tid >> 5, lane = tid & 31;

    if (blockIdx.x < LQ) {
        // ---- top-64 of 512 via warp-register bitonic selection (4 barriers) ----
        int i = blockIdx.x;
        float* sca = smem_f;                                             // 1536 f
        unsigned long long* ks = (unsigned long long*)(smem_f + 1536);   // 768 u64

        for (int j = tid; j < LQ; j += 256) {
            sca[j * 3 + 0] = xyz[j * 9 + 3];
            sca[j * 3 + 1] = xyz[j * 9 + 4];
            sca[j * 3 + 2] = xyz[j * 9 + 5];
        }
        __syncthreads();
        float cx = sca[i * 3 + 0], cy = sca[i * 3 + 1], cz = sca[i * 3 + 2];

        int j0 = w * 64 + lane;
        int j1 = j0 + 32;
        float dx0 = sca[j0 * 3 + 0] - cx, dy0 = sca[j0 * 3 + 1] - cy, dz0 = sca[j0 * 3 + 2] - cz;
        float d20 = dx0 * dx0 + dy0 * dy0 + dz0 * dz0;
        if (j0 == i) d20 += 1e9f;
        float dx1 = sca[j1 * 3 + 0] - cx, dy1 = sca[j1 * 3 + 1] - cy, dz1 = sca[j1 * 3 + 2] - cz;
        float d21 = dx1 * dx1 + dy1 * dy1 + dz1 * dz1;
        if (j1 == i) d21 += 1e9f;
        unsigned long long k0 = (((unsigned long long)__float_as_uint(d20)) << 32) | (unsigned)j0;
        unsigned long long k1 = (((unsigned long long)__float_as_uint(d21)) << 32) | (unsigned)j1;

        sort64(k0, k1, (w & 1) == 0, lane);     // even warps asc, odd desc
        ks[w * 64 + lane] = k0;
        ks[w * 64 + 32 + lane] = k1;
        __syncthreads();

        // round 1: 512 -> 256 (warps 0..3), write to double buffer ks[512..]
        if (w < 4) {
            int ba = (2 * w) * 64, bb = (2 * w + 1) * 64;
            unsigned long long a0 = ks[ba + lane], a1 = ks[ba + 32 + lane];
            unsigned long long c0 = ks[bb + lane], c1 = ks[bb + 32 + lane];
            k0 = (a0 < c0) ? a0 : c0;
            k1 = (a1 < c1) ? a1 : c1;
            merge64(k0, k1, (w & 1) == 0, lane);
            ks[512 + w * 64 + lane] = k0;
            ks[512 + w * 64 + 32 + lane] = k1;
        }
        __syncthreads();

        // round 2: 256 -> 128 (warps 0..1), write back to ks[0..127]
        if (w < 2) {
            int ba = 512 + (2 * w) * 64, bb = 512 + (2 * w + 1) * 64;
            unsigned long long a0 = ks[ba + lane], a1 = ks[ba + 32 + lane];
            unsigned long long c0 = ks[bb + lane], c1 = ks[bb + 32 + lane];
            k0 = (a0 < c0) ? a0 : c0;
            k1 = (a1 < c1) ? a1 : c1;
            merge64(k0, k1, (w & 1) == 0, lane);
            ks[w * 64 + lane] = k0;
            ks[w * 64 + 32 + lane] = k1;
        }
        __syncthreads();

        // round 3: 128 -> 64 (warp 0); set semantics — no final merge needed
        if (w == 0) {
            unsigned long long a0 = ks[lane],      a1 = ks[32 + lane];
            unsigned long long c0 = ks[64 + lane], c1 = ks[96 + lane];
            k0 = (a0 < c0) ? a0 : c0;
            k1 = (a1 < c1) ? a1 : c1;
            g_nbr[i * KNN + lane]      = (int)(k0 & 0xffffffffull);
            g_nbr[i * KNN + 32 + lane] = (int)(k1 & 0xffffffffull);
        }
    } else if (blockIdx.x < LQ + 64) {
        // ---- node features: 8 residues per block, one per warp ----
        int l = (blockIdx.x - LQ) * 8 + w;
        float* sx = smem_f + w * 312;

        float m[8]; float s0 = 0.f;
#pragma unroll
        for (int q = 0; q < 8; q++) { m[q] = msa[l * DM + lane + 32 * q]; s0 += m[q]; }
        float mu = wsum(s0) * (1.f / DM);
        float v0 = 0.f;
#pragma unroll
        for (int q = 0; q < 8; q++) { float d = m[q] - mu; v0 += d * d; }
        float rs = rsqrtf(wsum(v0) * (1.f / DM) + 1e-5f);
#pragma unroll
        for (int q = 0; q < 8; q++) {
            int c = lane + 32 * q;
            sx[c] = (m[q] - mu) * rs * g_msa[c] + b_msa[c];
        }
        if (lane < 21) sx[DM + lane] = seq1hot[l * 21 + lane];
        {
            float st = state[l * DS + lane];
            float mu2 = wsum(st) * (1.f / DS);
            float d = st - mu2;
            float rs2 = rsqrtf(wsum(d * d) * (1.f / DS) + 1e-5f);
            sx[DM + 21 + lane] = d * rs2 * g_state[lane] + b_state[lane];
        }
        __syncwarp();

        float a0 = b_x[lane], a1 = 0.f, a2 = 0.f, a3 = 0.f;
        for (int c = 0; c < 308; c += 4) {
            a0 = fmaf(sx[c + 0], __ldg(W_x + (c + 0) * NL0 + lane), a0);
            a1 = fmaf(sx[c + 1], __ldg(W_x + (c + 1) * NL0 + lane), a1);
            a2 = fmaf(sx[c + 2], __ldg(W_x + (c + 2) * NL0 + lane), a2);
            a3 = fmaf(sx[c + 3], __ldg(W_x + (c + 3) * NL0 + lane), a3);
        }
        float acc = (a0 + a1) + (a2 + a3) + sx[308] * __ldg(W_x + 308 * NL0 + lane);

        float mu3 = wsum(acc) * (1.f / NL0);
        float d3 = acc - mu3;
        float rs3 = rsqrtf(wsum(d3 * d3) * (1.f / NL0) + 1e-5f);
        g_node_feat[l * NL0 + lane] = d3 * rs3 * g_node[lane] + b_node[lane];
    } else {
        // ---- weight prep: pad W2, fold pair-LN into W_e1 ----
        for (int i = tid; i < MH * 48; i += 256) {
            int h = i / 48, c = i - h * 48;
            g_W2pad[i] = (c < MOUT) ? W2[h * MOUT + c] : 0.f;
        }
        if (tid < 48) g_b2pad[tid] = (tid < MOUT) ? b2[tid] : 0.f;
        for (int i = tid; i < DP * 32; i += 256) {
            int c = i >> 5;
            g_We1g[i] = g_pair[c] * W_e1[i];
        }
        if (tid < 32) {
            float s1 = 0.f, s2 = 0.f;
            for (int c = 0; c < DP; c++) {
                float wv = W_e1[c * 32 + tid];
                s1 = fmaf(g_pair[c], wv, s1);
                s2 = fmaf(b_pair[c], wv, s2);
            }
            g_S1[tid] = s1;
            g_S2[tid] = s2 + b_e1[tid];
        }
    }
}

// ---------------- Kernel B: half-residue (32 pairs) edge MLP ----------------
// smem layout (floats), P=32 pairs, stride 33
#define OFF_INVT   0        // 103*33 = 3399
#define OFF_BUF    3399     // 128*33 = 4224 (full pn tile; later rows 0..63 = hT)
#define OFF_GVGD   5511     // aliases BUF rows 64.. (dead after GEMM1); 32*6
#define OFF_MURS   7623     // 64 (mu,rs per pair)
#define OFF_HBASE  7687     // 64
#define OFF_GNE1   7751     // 32
#define OFF_BNE1   7783     // 32
#define OFF_NODEI  7815     // 32
#define OFF_CA     7847     // 4
#define OFF_WV     7851     // 12
#define OFF_NBR    7863     // 32 ints
#define OFF_RELHAT 7895     // 32*3
#define SMEMF      7991

__global__ void __launch_bounds__(128, 7) pair_kernel(
    const float* __restrict__ xyz, const float* __restrict__ pair,
    const float* __restrict__ g_ne1, const float* __restrict__ b_ne1,
    const float* __restrict__ W1, const float* __restrict__ b1,
    const float* __restrict__ Wv)
{
    extern __shared__ float s[];
    int l  = blockIdx.x >> 1;
    int ph = blockIdx.x & 1;          // pair half: pairs ph*32 .. ph*32+31
    int tid = threadIdx.x;
    int w = tid >> 5, lane = tid & 31;

    // ---- front-batched loads: neighbors + all 32 pair rows (MLP ~32) ----
    int jj[8];
#pragma unroll
    for (int t = 0; t < 8; t++)
        jj[t] = __ldg(g_nbr + l * KNN + ph * 32 + t * 4 + w);
    float A0[8], A1[8], A2[8], A3[8];
#pragma unroll
    for (int t = 0; t < 8; t++) {
        const float* prow = pair + ((size_t)l * LQ + jj[t]) * DP;
        A0[t] = __ldcs(prow + lane);
        A1[t] = __ldcs(prow + lane + 32);
        A2[t] = __ldcs(prow + lane + 64);
        A3[t] = __ldcs(prow + lane + 96);
    }

    // ---- stage small vectors ----
    if (tid < 32) {
        s[OFF_GNE1 + tid] = g_ne1[tid];
        s[OFF_BNE1 + tid] = b_ne1[tid];
        s[OFF_NODEI + tid] = g_node_feat[l * NL0 + tid];
        ((int*)(s + OFF_NBR))[tid] = g_nbr[l * KNN + ph * 32 + tid];
    }
    if (tid < 3) s[OFF_CA + tid] = xyz[l * 9 + 3 + tid];
    if (tid < 9) s[OFF_WV + tid] = Wv[tid];
    __syncthreads();

    // ---- hbase: node_i part of MLP1 (warps 0,1) ----
    if (tid < 64) {
        float a = b1[tid];
#pragma unroll
        for (int c = 0; c < 32; c++)
            a = fmaf(s[OFF_NODEI + c], __ldg(W1 + c * 64 + tid), a);
        s[OFF_HBASE + tid] = a;
    }

    // ---- P1: stats + full pn staging + geometry ----
    float ca0 = s[OFF_CA + 0], ca1 = s[OFF_CA + 1], ca2 = s[OFF_CA + 2];
#pragma unroll
    for (int t = 0; t < 8; t++) {
        int p = t * 4 + w;
        int j = jj[t];
        float a0 = A0[t], a1 = A1[t], a2 = A2[t], a3 = A3[t];
        float sum = a0 + a1 + a2 + a3;
        float ssq = a0 * a0 + a1 * a1 + a2 * a2 + a3 * a3;
        wsum2(sum, ssq);
        float mu = sum * (1.f / DP);
        float var = ssq * (1.f / DP) - mu * mu;
        float rs = rsqrtf(var + 1e-5f);
        s[OFF_BUF + lane * 33 + p] = a0;
        s[OFF_BUF + (lane + 32) * 33 + p] = a1;
        s[OFF_BUF + (lane + 64) * 33 + p] = a2;
        s[OFF_BUF + (lane + 96) * 33 + p] = a3;
        if (lane == 0) { s[OFF_MURS + 2 * p] = mu; s[OFF_MURS + 2 * p + 1] = rs; }

        s[OFF_INVT + lane * 33 + p] = g_node_feat[j * NL0 + lane];
        float cj0 = xyz[j * 9 + 3], cj1 = xyz[j * 9 + 4], cj2 = xyz[j * 9 + 5];
        float r0 = cj0 - ca0, r1 = cj1 - ca1, r2 = cj2 - ca2;
        float r = sqrtf(r0 * r0 + r1 * r1 + r2 * r2 + 1e-8f);
        {
            float c1 = (20.f / 35.f) * lane;
            float u = (r - c1) * 1.8f;
            s[OFF_INVT + (64 + lane) * 33 + p] = __expf(-u * u);
            if (lane < 4) {
                float c2 = (20.f / 35.f) * (lane + 32);
                float u2 = (r - c2) * 1.8f;
                s[OFF_INVT + (96 + lane) * 33 + p] = __expf(-u2 * u2);
            }
        }
        if (lane < 3) {
            float rel = (lane == 0) ? r0 : ((lane == 1) ? r1 : r2);
            s[OFF_RELHAT + p * 3 + lane] = rel / r;
            float b0 = xyz[j * 9 + lane * 3 + 0] - cj0;
            float b1v = xyz[j * 9 + lane * 3 + 1] - cj1;
            float b2v = xyz[j * 9 + lane * 3 + 2] - cj2;
            s[OFF_INVT + (100 + lane) * 33 + p] = sqrtf(b0 * b0 + b1v * b1v + b2v * b2v + 1e-8f);
        }
    }
    __syncthreads();

    int row = lane;                 // pair index within half
    int col0_8 = w * 8;

    // ---- GEMM1 (single 128-row pass) + LN-fold finalize -> E_pre into INVT rows 32..63 ----
    {
        float acc1[8];
#pragma unroll
        for (int jj2 = 0; jj2 < 8; jj2++) acc1[jj2] = 0.f;
#pragma unroll 2
        for (int c = 0; c < 128; c++) {
            float a = s[OFF_BUF + c * 33 + row];
            const float4* wp = (const float4*)(g_We1g + c * 32 + col0_8);
            float4 w0 = __ldg(wp), w1 = __ldg(wp + 1);
            acc1[0] = fmaf(a, w0.x, acc1[0]); acc1[1] = fmaf(a, w0.y, acc1[1]);
            acc1[2] = fmaf(a, w0.z, acc1[2]); acc1[3] = fmaf(a, w0.w, acc1[3]);
            acc1[4] = fmaf(a, w1.x, acc1[4]); acc1[5] = fmaf(a, w1.y, acc1[5]);
            acc1[6] = fmaf(a, w1.z, acc1[6]); acc1[7] = fmaf(a, w1.w, acc1[7]);
        }
        float mu = s[OFF_MURS + 2 * row];
        float rs = s[OFF_MURS + 2 * row + 1];
#pragma unroll
        for (int jj2 = 0; jj2 < 8; jj2++) {
            float e = rs * acc1[jj2] - rs * mu * __ldg(g_S1 + col0_8 + jj2) + __ldg(g_S2 + col0_8 + jj2);
            s[OFF_INVT + (32 + col0_8 + jj2) * 33 + row] = e;
        }
    }
    __syncthreads();

    // ---- LN over e_pre (32) per pair (E[x^2] form) ----
#pragma unroll 2
    for (int t = 0; t < 8; t++) {
        int p = t * 4 + w;
        float x = s[OFF_INVT + (32 + lane) * 33 + p];
        float sum = x, ssq = x * x;
        wsum2(sum, ssq);
        float mu = sum * (1.f / 32.f);
        float var = ssq * (1.f / 32.f) - mu * mu;
        float rs = rsqrtf(var + 1e-5f);
        s[OFF_INVT + (32 + lane) * 33 + p] = (x - mu) * rs * s[OFF_GNE1 + lane] + s[OFF_BNE1 + lane];
    }
    __syncthreads();

    // ---- GEMM2: H[32x64] = relu(hbase + INV[32x103] @ W1[32:,:]) -> BUF rows 0..63 ----
    {
        int col0 = w * 16;
        const float* w1base = W1 + 32 * 64 + col0;
        float acc[16];
#pragma unroll
        for (int jj2 = 0; jj2 < 16; jj2++) acc[jj2] = s[OFF_HBASE + col0 + jj2];
#pragma unroll 2
        for (int cc = 0; cc < 103; cc++) {
            float a = s[OFF_INVT + cc * 33 + row];
            const float4* wp = (const float4*)(w1base + cc * 64);
            float4 w0 = __ldg(wp), w1v = __ldg(wp + 1), w2v = __ldg(wp + 2), w3 = __ldg(wp + 3);
            acc[0]  = fmaf(a, w0.x, acc[0]);  acc[1]  = fmaf(a, w0.y, acc[1]);
            acc[2]  = fmaf(a, w0.z, acc[2]);  acc[3]  = fmaf(a, w0.w, acc[3]);
            acc[4]  = fmaf(a, w1v.x, acc[4]); acc[5]  = fmaf(a, w1v.y, acc[5]);
            acc[6]  = fmaf(a, w1v.z, acc[6]); acc[7]  = fmaf(a, w1v.w, acc[7]);
            acc[8]  = fmaf(a, w2v.x, acc[8]); acc[9]  = fmaf(a, w2v.y, acc[9]);
            acc[10] = fmaf(a, w2v.z, acc[10]); acc[11] = fmaf(a, w2v.w, acc[11]);
            acc[12] = fmaf(a, w3.x, acc[12]); acc[13] = fmaf(a, w3.y, acc[13]);
            acc[14] = fmaf(a, w3.z, acc[14]); acc[15] = fmaf(a, w3.w, acc[15]);
        }
#pragma unroll
        for (int jj2 = 0; jj2 < 16; jj2++)
            s[OFF_BUF + (col0 + jj2) * 33 + row] = fmaxf(acc[jj2], 0.f);
    }
    __syncthreads();

    // ---- GEMM3: M[32x38] = H @ W2pad + b2; m0 half-sums + gv/gd (GVGD aliases BUF rows 64+) ----
    {
        int col0 = w * 12;
        float acc[12];
#pragma unroll
        for (int jj2 = 0; jj2 < 12; jj2++) acc[jj2] = g_b2pad[col0 + jj2];
#pragma unroll 2
        for (int h = 0; h < 64; h++) {
            float a = s[OFF_BUF + h * 33 + row];
            const float4* wp = (const float4*)(g_W2pad + h * 48 + col0);
            float4 w0 = __ldg(wp), w1v = __ldg(wp + 1), w2v = __ldg(wp + 2);
            acc[0]  = fmaf(a, w0.x, acc[0]);  acc[1]  = fmaf(a, w0.y, acc[1]);
            acc[2]  = fmaf(a, w0.z, acc[2]);  acc[3]  = fmaf(a, w0.w, acc[3]);
            acc[4]  = fmaf(a, w1v.x, acc[4]); acc[5]  = fmaf(a, w1v.y, acc[5]);
            acc[6]  = fmaf(a, w1v.z, acc[6]); acc[7]  = fmaf(a, w1v.w, acc[7]);
            acc[8]  = fmaf(a, w2v.x, acc[8]); acc[9]  = fmaf(a, w2v.y, acc[9]);
            acc[10] = fmaf(a, w2v.z, acc[10]); acc[11] = fmaf(a, w2v.w, acc[11]);
        }
#pragma unroll
        for (int jj2 = 0; jj2 < 12; jj2++) {
            int cg = col0 + jj2;
            if (cg < 32) {
                float red = wsum(acc[jj2]);      // sum over 32 pairs (lanes)
                if (lane == 0) g_m0p[(l * 2 + ph) * 32 + cg] = red;
            } else if (cg < 38) {
                s[OFF_GVGD + row * 6 + (cg - 32)] = acc[jj2];
            }
        }
    }
    __syncthreads();

    // ---- out1 half-sums over the 32 pairs (warp 0) ----
    if (tid < 32) {
        int p = lane;
        int j = ((const int*)(s + OFF_NBR))[p];
        float cj0 = xyz[j * 9 + 3], cj1 = xyz[j * 9 + 4], cj2 = xyz[j * 9 + 5];
        float v1[3][3];
#pragma unroll
        for (int c = 0; c < 3; c++) {
            v1[c][0] = xyz[j * 9 + c * 3 + 0] - cj0;
            v1[c][1] = xyz[j * 9 + c * 3 + 1] - cj1;
            v1[c][2] = xyz[j * 9 + c * 3 + 2] - cj2;
        }
        float rh[3] = { s[OFF_RELHAT + p * 3 + 0], s[OFF_RELHAT + p * 3 + 1], s[OFF_RELHAT + p * 3 + 2] };
#pragma unroll
        for (int o = 0; o < 3; o++) {
            float gvv = s[OFF_GVGD + p * 6 + o];
            float gdd = s[OFF_GVGD + p * 6 + 3 + o];
            float wv0 = s[OFF_WV + o * 3 + 0], wv1 = s[OFF_WV + o * 3 + 1], wv2 = s[OFF_WV + o * 3 + 2];
#pragma unroll
            for (int d = 0; d < 3; d++) {
                float vm = wv0 * v1[0][d] + wv1 * v1[1][d] + wv2 * v1[2][d];
                float contrib = gvv * vm + gdd * rh[d];
                float red = wsum(contrib);
                if (lane == 0) g_o1p[(l * 2 + ph) * 12 + o * 3 + d] = red;
            }
        }
    }
}

// ---------------- Kernel C: epilogue (combine halves, Wself, LN, lddt, xyz) ----------------
__global__ void __launch_bounds__(256) epi_kernel(
    const float* __restrict__ xyz,
    const float* __restrict__ Wself, const float* __restrict__ W_lddt,
    const float* __restrict__ b_lddt,
    const float* __restrict__ g_state, const float* __restrict__ b_state,
    float* __restrict__ out)
{
    int w = threadIdx.x >> 5, lane = threadIdx.x & 31;
    int l = blockIdx.x * 8 + w;

    float acc = (g_m0p[(l * 2 + 0) * 32 + lane] + g_m0p[(l * 2 + 1) * 32 + lane]) * (1.f / KNN);
#pragma unroll
    for (int c = 0; c < 32; c++)
        acc = fmaf(g_node_feat[l * NL0 + c], __ldg(Wself + c * 32 + lane), acc);
    float mu = wsum(acc) * (1.f / 32.f);
    float d = acc - mu;
    float rs = rsqrtf(wsum(d * d) * (1.f / 32.f) + 1e-5f);
    float y = d * rs * g_state[lane] + b_state[lane];
    float tot = wsum(y * W_lddt[lane]);
    if (lane == 0)
        out[LQ * 9 + l] = 1.f / (1.f + expf(-(tot + b_lddt[0])));
    if (lane < 9) {
        int o = lane / 3, dd = lane % 3;
        float o1 = (g_o1p[(l * 2 + 0) * 12 + lane] + g_o1p[(l * 2 + 1) * 12 + lane]) * (1.f / KNN);
        float o1r1 = (g_o1p[(l * 2 + 0) * 12 + 3 + dd] + g_o1p[(l * 2 + 1) * 12 + 3 + dd]) * (1.f / KNN);
        float can = xyz[l * 9 + 3 + dd] + o1r1;
        float val = o1 + ((l == 0) ? 0.f : can);
        out[(l * 3 + o) * 3 + dd] = val;
    }
}

// ---------------- launch ----------------
extern "C" void kernel_launch(void* const* d_in, const int* in_sizes, int n_in,
                              void* d_out, int out_size)
{
    const float* xyz     = (const float*)d_in[0];
    const float* state   = (const float*)d_in[1];
    const float* msa     = (const float*)d_in[2];
    const float* pair    = (const float*)d_in[3];
    const float* seq1hot = (const float*)d_in[4];
    const float* g_msa   = (const float*)d_in[8];
    const float* b_msa   = (const float*)d_in[9];
    const float* g_pair  = (const float*)d_in[10];
    const float* b_pair  = (const float*)d_in[11];
    const float* g_state = (const float*)d_in[12];
    const float* b_state = (const float*)d_in[13];
    const float* W_x     = (const float*)d_in[14];
    const float* b_x     = (const float*)d_in[15];
    const float* g_node  = (const float*)d_in[16];
    const float* b_node  = (const float*)d_in[17];
    const float* W_e1    = (const float*)d_in[18];
    const float* b_e1    = (const float*)d_in[19];
    const float* g_ne1   = (const float*)d_in[20];
    const float* b_ne1   = (const float*)d_in[21];
    const float* W1      = (const float*)d_in[22];
    const float* b1      = (const float*)d_in[23];
    const float* W2      = (const float*)d_in[24];
    const float* b2      = (const float*)d_in[25];
    const float* Wv      = (const float*)d_in[26];
    const float* Wself   = (const float*)d_in[27];
    const float* W_lddt  = (const float*)d_in[28];
    const float* b_lddt  = (const float*)d_in[29];
    float* out = (float*)d_out;

    prep_kernel<<<LQ + 64 + 1, 256>>>(xyz, msa, seq1hot, state,
                                      g_msa, b_msa, g_state, b_state,
                                      W_x, b_x, g_node, b_node, W2, b2,
                                      g_pair, b_pair, W_e1, b_e1);
    pair_kernel<<<LQ * 2, 128, SMEMF * sizeof(float)>>>(
        xyz, pair, g_ne1, b_ne1, W1, b1, Wv);
    epi_kernel<<<LQ / 8, 256>>>(xyz, Wself, W_lddt, b_lddt, g_state, b_state, out);
}

// round 13
// speedup vs baseline: 1.0252x; 1.0252x over previous
#include <cuda_runtime.h>
#include <math.h>

#define LQ    512
#define KNN   64
#define DM    256
#define DP    128
#define DS    32
#define NL0   32
#define NRBF  36
#define MH    64
#define MOUT  38

// ---------------- scratch (static device arrays; no allocation) ----------------
__device__ float g_node_feat[LQ * NL0];
__device__ int   g_nbr[LQ * KNN];
__device__ __align__(16) float g_W2pad[MH * 48];
__device__ __align__(16) float g_b2pad[48];
__device__ __align__(16) float g_We1g[DP * 32];   // g_pair[c] * W_e1[c][j]
__device__ float g_S1[32];          // sum_c g_pair[c]*W_e1[c][j]
__device__ float g_S2[32];          // sum_c b_pair[c]*W_e1[c][j] + b_e1[j]
__device__ float g_m0p[LQ * 2 * 32];  // per-half m0 column sums
__device__ float g_o1p[LQ * 2 * 12];  // per-half out1 sums (9 used)

__device__ __forceinline__ float wsum(float v) {
#pragma unroll
    for (int o = 16; o; o >>= 1) v += __shfl_xor_sync(0xffffffffu, v, o);
    return v;
}
__device__ __forceinline__ void wsum2(float& a, float& b) {
#pragma unroll
    for (int o = 16; o; o >>= 1) {
        a += __shfl_xor_sync(0xffffffffu, a, o);
        b += __shfl_xor_sync(0xffffffffu, b, o);
    }
}

// ---- packed f32x2 helpers (Blackwell sm_100+; lanewise exact fp32) ----
__device__ __forceinline__ unsigned long long pack2(float a) {
    unsigned long long r;
    asm("mov.b64 %0, {%1, %1};" : "=l"(r) : "f"(a));
    return r;
}
__device__ __forceinline__ unsigned long long pack2f(float lo, float hi) {
    unsigned long long r;
    asm("mov.b64 %0, {%1, %2};" : "=l"(r) : "f"(lo), "f"(hi));
    return r;
}
__device__ __forceinline__ void ffma2(unsigned long long& d, unsigned long long a, unsigned long long b) {
    asm("fma.rn.f32x2 %0, %1, %2, %0;" : "+l"(d) : "l"(a), "l"(b));
}
__device__ __forceinline__ float2 unpack2(unsigned long long v) {
    float x, y;
    asm("mov.b64 {%0, %1}, %2;" : "=f"(x), "=f"(y) : "l"(v));
    return make_float2(x, y);
}

// ---- warp-register bitonic helpers (64 keys per warp, 2 per lane) ----
__device__ __forceinline__ unsigned long long shflx64(unsigned long long v, int m) {
    unsigned lo = __shfl_xor_sync(0xffffffffu, (unsigned)v, m);
    unsigned hi = __shfl_xor_sync(0xffffffffu, (unsigned)(v >> 32), m);
    return ((unsigned long long)hi << 32) | lo;
}
__device__ __forceinline__ void ce64(unsigned long long& r, int j, bool up, int lane) {
    unsigned long long p = shflx64(r, j);
    bool lower = ((lane & j) == 0);
    bool kmin = (lower == up);
    bool pless = (p < r);
    r = (kmin == pless) ? p : r;
}
__device__ __forceinline__ void sort64(unsigned long long& r0, unsigned long long& r1,
                                       bool dir, int lane) {
#pragma unroll
    for (int k = 2; k <= 64; k <<= 1) {
#pragma unroll 6
        for (int j = k >> 1; j > 0; j >>= 1) {
            if (j == 32) {
                unsigned long long lo = (r0 < r1) ? r0 : r1;
                unsigned long long hi = (r0 < r1) ? r1 : r0;
                r0 = dir ? lo : hi; r1 = dir ? hi : lo;
            } else {
                bool up0, up1;
                if (k == 64)      { up0 = dir;  up1 = dir;  }
                else if (k == 32) { up0 = dir;  up1 = !dir; }
                else { bool u = (((lane & k) == 0) == dir); up0 = u; up1 = u; }
                ce64(r0, j, up0, lane);
                ce64(r1, j, up1, lane);
            }
        }
    }
}
__device__ __forceinline__ void merge64(unsigned long long& r0, unsigned long long& r1,
                                        bool dir, int lane) {
    {
        unsigned long long lo = (r0 < r1) ? r0 : r1;
        unsigned long long hi = (r0 < r1) ? r1 : r0;
        r0 = dir ? lo : hi; r1 = dir ? hi : lo;
    }
#pragma unroll
    for (int j = 16; j > 0; j >>= 1) {
        ce64(r0, j, dir, lane);
        ce64(r1, j, dir, lane);
    }
}

// ---------------- Kernel A: node features (0..63) + weight prep (64) + topk (65..576) ----------------
__global__ void __launch_bounds__(256) prep_kernel(
    const float* __restrict__ xyz,
    const float* __restrict__ msa, const float* __restrict__ seq1hot,
    const float* __restrict__ state,
    const float* __restrict__ g_msa, const float* __restrict__ b_msa,
    const float* __restrict__ g_state, const float* __restrict__ b_state,
    const float* __restrict__ W_x, const float* __restrict__ b_x,
    const float* __restrict__ g_node, const float* __restrict__ b_node,
    const float* __restrict__ W2, const float* __restrict__ b2,
    const float* __restrict__ g_pair, const float* __restrict__ b_pair,
    const float* __restrict__ W_e1, const float* __restrict__ b_e1)
{
    __shared__ __align__(16) float smem_f[3072];
    int tid = threadIdx.x;
    int w = tid >> 5, lane = tid & 31;

    if (blockIdx.x < 64) {
        // ---- node features: 8 residues per block, one per warp ----
        int l = blockIdx.x * 8 + w;
        float* sx = smem_f + w * 312;

        float m[8]; float s0 = 0.f;
#pragma unroll
        for (int q = 0; q < 8; q++) { m[q] = msa[l * DM + lane + 32 * q]; s0 += m[q]; }
        float mu = wsum(s0) * (1.f / DM);
        float v0 = 0.f;
#pragma unroll
        for (int q = 0; q < 8; q++) { float d = m[q] - mu; v0 += d * d; }
        float rs = rsqrtf(wsum(v0) * (1.f / DM) + 1e-5f);
#pragma unroll
        for (int q = 0; q < 8; q++) {
            int c = lane + 32 * q;
            sx[c] = (m[q] - mu) * rs * g_msa[c] + b_msa[c];
        }
        if (lane < 21) sx[DM + lane] = seq1hot[l * 21 + lane];
        {
            float st = state[l * DS + lane];
            float mu2 = wsum(st) * (1.f / DS);
            float d = st - mu2;
            float rs2 = rsqrtf(wsum(d * d) * (1.f / DS) + 1e-5f);
            sx[DM + 21 + lane] = d * rs2 * g_state[lane] + b_state[lane];
        }
        __syncwarp();

        float a0 = b_x[lane], a1 = 0.f, a2 = 0.f, a3 = 0.f;
        for (int c = 0; c < 308; c += 4) {
            a0 = fmaf(sx[c + 0], __ldg(W_x + (c + 0) * NL0 + lane), a0);
            a1 = fmaf(sx[c + 1], __ldg(W_x + (c + 1) * NL0 + lane), a1);
            a2 = fmaf(sx[c + 2], __ldg(W_x + (c + 2) * NL0 + lane), a2);
            a3 = fmaf(sx[c + 3], __ldg(W_x + (c + 3) * NL0 + lane), a3);
        }
        float acc = (a0 + a1) + (a2 + a3) + sx[308] * __ldg(W_x + 308 * NL0 + lane);

        float mu3 = wsum(acc) * (1.f / NL0);
        float d3 = acc - mu3;
        float rs3 = rsqrtf(wsum(d3 * d3) * (1.f / NL0) + 1e-5f);
        g_node_feat[l * NL0 + lane] = d3 * rs3 * g_node[lane] + b_node[lane];
    } else if (blockIdx.x == 64) {
        // ---- weight prep: pad W2, fold pair-LN into W_e1 ----
        for (int i = tid; i < MH * 48; i += 256) {
            int h = i / 48, c = i - h * 48;
            g_W2pad[i] = (c < MOUT) ? W2[h * MOUT + c] : 0.f;
        }
        if (tid < 48) g_b2pad[tid] = (tid < MOUT) ? b2[tid] : 0.f;
        for (int i = tid; i < DP * 32; i += 256) {
            int c = i >> 5;
            g_We1g[i] = g_pair[c] * W_e1[i];
        }
        if (tid < 32) {
            float s1 = 0.f, s2 = 0.f;
            for (int c = 0; c < DP; c++) {
                float wv = W_e1[c * 32 + tid];
                s1 = fmaf(g_pair[c], wv, s1);
                s2 = fmaf(b_pair[c], wv, s2);
            }
            g_S1[tid] = s1;
            g_S2[tid] = s2 + b_e1[tid];
        }
    } else {
        // ---- top-64 of 512 via warp-register bitonic selection (4 barriers) ----
        int i = blockIdx.x - 65;
        float* sca = smem_f;                                             // 1536 f
        unsigned long long* ks = (unsigned long long*)(smem_f + 1536);   // 768 u64

        for (int j = tid; j < LQ; j += 256) {
            sca[j * 3 + 0] = xyz[j * 9 + 3];
            sca[j * 3 + 1] = xyz[j * 9 + 4];
            sca[j * 3 + 2] = xyz[j * 9 + 5];
        }
        __syncthreads();
        float cx = sca[i * 3 + 0], cy = sca[i * 3 + 1], cz = sca[i * 3 + 2];

        int j0 = w * 64 + lane;
        int j1 = j0 + 32;
        float dx0 = sca[j0 * 3 + 0] - cx, dy0 = sca[j0 * 3 + 1] - cy, dz0 = sca[j0 * 3 + 2] - cz;
        float d20 = dx0 * dx0 + dy0 * dy0 + dz0 * dz0;
        if (j0 == i) d20 += 1e9f;
        float dx1 = sca[j1 * 3 + 0] - cx, dy1 = sca[j1 * 3 + 1] - cy, dz1 = sca[j1 * 3 + 2] - cz;
        float d21 = dx1 * dx1 + dy1 * dy1 + dz1 * dz1;
        if (j1 == i) d21 += 1e9f;
        unsigned long long k0 = (((unsigned long long)__float_as_uint(d20)) << 32) | (unsigned)j0;
        unsigned long long k1 = (((unsigned long long)__float_as_uint(d21)) << 32) | (unsigned)j1;

        sort64(k0, k1, (w & 1) == 0, lane);
        ks[w * 64 + lane] = k0;
        ks[w * 64 + 32 + lane] = k1;
        __syncthreads();

        if (w < 4) {
            int ba = (2 * w) * 64, bb = (2 * w + 1) * 64;
            unsigned long long a0 = ks[ba + lane], a1 = ks[ba + 32 + lane];
            unsigned long long c0 = ks[bb + lane], c1 = ks[bb + 32 + lane];
            k0 = (a0 < c0) ? a0 : c0;
            k1 = (a1 < c1) ? a1 : c1;
            merge64(k0, k1, (w & 1) == 0, lane);
            ks[512 + w * 64 + lane] = k0;
            ks[512 + w * 64 + 32 + lane] = k1;
        }
        __syncthreads();

        if (w < 2) {
            int ba = 512 + (2 * w) * 64, bb = 512 + (2 * w + 1) * 64;
            unsigned long long a0 = ks[ba + lane], a1 = ks[ba + 32 + lane];
            unsigned long long c0 = ks[bb + lane], c1 = ks[bb + 32 + lane];
            k0 = (a0 < c0) ? a0 : c0;
            k1 = (a1 < c1) ? a1 : c1;
            merge64(k0, k1, (w & 1) == 0, lane);
            ks[w * 64 + lane] = k0;
            ks[w * 64 + 32 + lane] = k1;
        }
        __syncthreads();

        if (w == 0) {
            unsigned long long a0 = ks[lane],      a1 = ks[32 + lane];
            unsigned long long c0 = ks[64 + lane], c1 = ks[96 + lane];
            k0 = (a0 < c0) ? a0 : c0;
            k1 = (a1 < c1) ? a1 : c1;
            g_nbr[i * KNN + lane]      = (int)(k0 & 0xffffffffull);
            g_nbr[i * KNN + 32 + lane] = (int)(k1 & 0xffffffffull);
        }
    }
}

// ---------------- Kernel B: half-residue (32 pairs) edge MLP ----------------
// smem layout (floats), P=32 pairs, stride 33
#define OFF_INVT   0        // 103*33 = 3399
#define OFF_BUF    3399     // 128*33 = 4224 (full pn tile; later rows 0..63 = hT)
#define OFF_GVGD   5511     // aliases BUF rows 64.. (dead after GEMM1); 32*6
#define OFF_MURS   7623     // 64 (mu,rs per pair)
#define OFF_HBASE  7687     // 64
#define OFF_GNE1   7751     // 32
#define OFF_BNE1   7783     // 32
#define OFF_NODEI  7815     // 32
#define OFF_CA     7847     // 4
#define OFF_WV     7851     // 12
#define OFF_NBR    7863     // 32 ints
#define OFF_RELHAT 7895     // 32*3
#define SMEMF      7991

__global__ void __launch_bounds__(128, 7) pair_kernel(
    const float* __restrict__ xyz, const float* __restrict__ pair,
    const float* __restrict__ g_ne1, const float* __restrict__ b_ne1,
    const float* __restrict__ W1, const float* __restrict__ b1,
    const float* __restrict__ Wv)
{
    extern __shared__ float s[];
    int l  = blockIdx.x >> 1;
    int ph = blockIdx.x & 1;
    int tid = threadIdx.x;
    int w = tid >> 5, lane = tid & 31;

    // ---- front-batched loads: neighbors + all 32 pair rows ----
    int jj[8];
#pragma unroll
    for (int t = 0; t < 8; t++)
        jj[t] = __ldg(g_nbr + l * KNN + ph * 32 + t * 4 + w);
    float A0[8], A1[8], A2[8], A3[8];
#pragma unroll
    for (int t = 0; t < 8; t++) {
        const float* prow = pair + ((size_t)l * LQ + jj[t]) * DP;
        A0[t] = __ldcs(prow + lane);
        A1[t] = __ldcs(prow + lane + 32);
        A2[t] = __ldcs(prow + lane + 64);
        A3[t] = __ldcs(prow + lane + 96);
    }

    // ---- stage small vectors ----
    if (tid < 32) {
        s[OFF_GNE1 + tid] = g_ne1[tid];
        s[OFF_BNE1 + tid] = b_ne1[tid];
        s[OFF_NODEI + tid] = g_node_feat[l * NL0 + tid];
        ((int*)(s + OFF_NBR))[tid] = g_nbr[l * KNN + ph * 32 + tid];
    }
    if (tid < 3) s[OFF_CA + tid] = xyz[l * 9 + 3 + tid];
    if (tid < 9) s[OFF_WV + tid] = Wv[tid];
    __syncthreads();

    // ---- hbase: node_i part of MLP1 (warps 0,1) ----
    if (tid < 64) {
        float a = b1[tid];
#pragma unroll
        for (int c = 0; c < 32; c++)
            a = fmaf(s[OFF_NODEI + c], __ldg(W1 + c * 64 + tid), a);
        s[OFF_HBASE + tid] = a;
    }

    // ---- P1: stats + full pn staging + geometry ----
    float ca0 = s[OFF_CA + 0], ca1 = s[OFF_CA + 1], ca2 = s[OFF_CA + 2];
#pragma unroll
    for (int t = 0; t < 8; t++) {
        int p = t * 4 + w;
        int j = jj[t];
        float a0 = A0[t], a1 = A1[t], a2 = A2[t], a3 = A3[t];
        float sum = a0 + a1 + a2 + a3;
        float ssq = a0 * a0 + a1 * a1 + a2 * a2 + a3 * a3;
        wsum2(sum, ssq);
        float mu = sum * (1.f / DP);
        float var = ssq * (1.f / DP) - mu * mu;
        float rs = rsqrtf(var + 1e-5f);
        s[OFF_BUF + lane * 33 + p] = a0;
        s[OFF_BUF + (lane + 32) * 33 + p] = a1;
        s[OFF_BUF + (lane + 64) * 33 + p] = a2;
        s[OFF_BUF + (lane + 96) * 33 + p] = a3;
        if (lane == 0) { s[OFF_MURS + 2 * p] = mu; s[OFF_MURS + 2 * p + 1] = rs; }

        s[OFF_INVT + lane * 33 + p] = g_node_feat[j * NL0 + lane];
        float cj0 = xyz[j * 9 + 3], cj1 = xyz[j * 9 + 4], cj2 = xyz[j * 9 + 5];
        float r0 = cj0 - ca0, r1 = cj1 - ca1, r2 = cj2 - ca2;
        float r = sqrtf(r0 * r0 + r1 * r1 + r2 * r2 + 1e-8f);
        {
            float c1 = (20.f / 35.f) * lane;
            float u = (r - c1) * 1.8f;
            s[OFF_INVT + (64 + lane) * 33 + p] = __expf(-u * u);
            if (lane < 4) {
                float c2 = (20.f / 35.f) * (lane + 32);
                float u2 = (r - c2) * 1.8f;
                s[OFF_INVT + (96 + lane) * 33 + p] = __expf(-u2 * u2);
            }
        }
        if (lane < 3) {
            float rel = (lane == 0) ? r0 : ((lane == 1) ? r1 : r2);
            s[OFF_RELHAT + p * 3 + lane] = rel / r;
            float b0 = xyz[j * 9 + lane * 3 + 0] - cj0;
            float b1v = xyz[j * 9 + lane * 3 + 1] - cj1;
            float b2v = xyz[j * 9 + lane * 3 + 2] - cj2;
            s[OFF_INVT + (100 + lane) * 33 + p] = sqrtf(b0 * b0 + b1v * b1v + b2v * b2v + 1e-8f);
        }
    }
    __syncthreads();

    int row = lane;
    int col0_8 = w * 8;

    // ---- GEMM1 (f32x2): 128-row pass + LN-fold -> E_pre into INVT rows 32..63 ----
    {
        unsigned long long acc1[4];
        acc1[0] = acc1[1] = acc1[2] = acc1[3] = 0ull;
#pragma unroll 2
        for (int c = 0; c < 128; c++) {
            unsigned long long ap = pack2(s[OFF_BUF + c * 33 + row]);
            const ulonglong2* wp = (const ulonglong2*)(g_We1g + c * 32 + col0_8);
            ulonglong2 w0 = wp[0], w1 = wp[1];
            ffma2(acc1[0], ap, w0.x); ffma2(acc1[1], ap, w0.y);
            ffma2(acc1[2], ap, w1.x); ffma2(acc1[3], ap, w1.y);
        }
        float mu = s[OFF_MURS + 2 * row];
        float rs = s[OFF_MURS + 2 * row + 1];
#pragma unroll
        for (int q = 0; q < 4; q++) {
            float2 v = unpack2(acc1[q]);
            int c0 = col0_8 + 2 * q;
            s[OFF_INVT + (32 + c0) * 33 + row] =
                rs * v.x - rs * mu * __ldg(g_S1 + c0) + __ldg(g_S2 + c0);
            s[OFF_INVT + (32 + c0 + 1) * 33 + row] =
                rs * v.y - rs * mu * __ldg(g_S1 + c0 + 1) + __ldg(g_S2 + c0 + 1);
        }
    }
    __syncthreads();

    // ---- LN over e_pre (32) per pair ----
#pragma unroll 2
    for (int t = 0; t < 8; t++) {
        int p = t * 4 + w;
        float x = s[OFF_INVT + (32 + lane) * 33 + p];
        float sum = x, ssq = x * x;
        wsum2(sum, ssq);
        float mu = sum * (1.f / 32.f);
        float var = ssq * (1.f / 32.f) - mu * mu;
        float rs = rsqrtf(var + 1e-5f);
        s[OFF_INVT + (32 + lane) * 33 + p] = (x - mu) * rs * s[OFF_GNE1 + lane] + s[OFF_BNE1 + lane];
    }
    __syncthreads();

    // ---- GEMM2 (f32x2): H[32x64] = relu(hbase + INV[32x103] @ W1[32:,:]) ----
    {
        int col0 = w * 16;
        const float* w1base = W1 + 32 * 64 + col0;
        unsigned long long acc[8];
#pragma unroll
        for (int q = 0; q < 8; q++)
            acc[q] = pack2f(s[OFF_HBASE + col0 + 2 * q], s[OFF_HBASE + col0 + 2 * q + 1]);
#pragma unroll 2
        for (int cc = 0; cc < 103; cc++) {
            unsigned long long ap = pack2(s[OFF_INVT + cc * 33 + row]);
            const ulonglong2* wp = (const ulonglong2*)(w1base + cc * 64);
            ulonglong2 w0 = wp[0], w1v = wp[1], w2v = wp[2], w3v = wp[3];
            ffma2(acc[0], ap, w0.x);  ffma2(acc[1], ap, w0.y);
            ffma2(acc[2], ap, w1v.x); ffma2(acc[3], ap, w1v.y);
            ffma2(acc[4], ap, w2v.x); ffma2(acc[5], ap, w2v.y);
            ffma2(acc[6], ap, w3v.x); ffma2(acc[7], ap, w3v.y);
        }
#pragma unroll
        for (int q = 0; q < 8; q++) {
            float2 v = unpack2(acc[q]);
            s[OFF_BUF + (col0 + 2 * q) * 33 + row] = fmaxf(v.x, 0.f);
            s[OFF_BUF + (col0 + 2 * q + 1) * 33 + row] = fmaxf(v.y, 0.f);
        }
    }
    __syncthreads();

    // ---- GEMM3 (f32x2): M[32x38] = H @ W2pad + b2; m0 half-sums + gv/gd ----
    {
        int col0 = w * 12;
        unsigned long long acc[6];
#pragma unroll
        for (int q = 0; q < 6; q++)
            acc[q] = pack2f(g_b2pad[col0 + 2 * q], g_b2pad[col0 + 2 * q + 1]);
#pragma unroll 2
        for (int h = 0; h < 64; h++) {
            unsigned long long ap = pack2(s[OFF_BUF + h * 33 + row]);
            const ulonglong2* wp = (const ulonglong2*)(g_W2pad + h * 48 + col0);
            ulonglong2 w0 = wp[0], w1v = wp[1], w2v = wp[2];
            ffma2(acc[0], ap, w0.x);  ffma2(acc[1], ap, w0.y);
            ffma2(acc[2], ap, w1v.x); ffma2(acc[3], ap, w1v.y);
            ffma2(acc[4], ap, w2v.x); ffma2(acc[5], ap, w2v.y);
        }
        float accs[12];
#pragma unroll
        for (int q = 0; q < 6; q++) {
            float2 v = unpack2(acc[q]);
            accs[2 * q] = v.x; accs[2 * q + 1] = v.y;
        }
#pragma unroll
        for (int jj2 = 0; jj2 < 12; jj2++) {
            int cg = col0 + jj2;
            if (cg < 32) {
                float red = wsum(accs[jj2]);
                if (lane == 0) g_m0p[(l * 2 + ph) * 32 + cg] = red;
            } else if (cg < 38) {
                s[OFF_GVGD + row * 6 + (cg - 32)] = accs[jj2];
            }
        }
    }
    __syncthreads();

    // ---- out1 half-sums over the 32 pairs (warp 0) ----
    if (tid < 32) {
        int p = lane;
        int j = ((const int*)(s + OFF_NBR))[p];
        float cj0 = xyz[j * 9 + 3], cj1 = xyz[j * 9 + 4], cj2 = xyz[j * 9 + 5];
        float v1[3][3];
#pragma unroll
        for (int c = 0; c < 3; c++) {
            v1[c][0] = xyz[j * 9 + c * 3 + 0] - cj0;
            v1[c][1] = xyz[j * 9 + c * 3 + 1] - cj1;
            v1[c][2] = xyz[j * 9 + c * 3 + 2] - cj2;
        }
        float rh[3] = { s[OFF_RELHAT + p * 3 + 0], s[OFF_RELHAT + p * 3 + 1], s[OFF_RELHAT + p * 3 + 2] };
#pragma unroll
        for (int o = 0; o < 3; o++) {
            float gvv = s[OFF_GVGD + p * 6 + o];
            float gdd = s[OFF_GVGD + p * 6 + 3 + o];
            float wv0 = s[OFF_WV + o * 3 + 0], wv1 = s[OFF_WV + o * 3 + 1], wv2 = s[OFF_WV + o * 3 + 2];
#pragma unroll
            for (int d = 0; d < 3; d++) {
                float vm = wv0 * v1[0][d] + wv1 * v1[1][d] + wv2 * v1[2][d];
                float contrib = gvv * vm + gdd * rh[d];
                float red = wsum(contrib);
                if (lane == 0) g_o1p[(l * 2 + ph) * 12 + o * 3 + d] = red;
            }
        }
    }
}

// ---------------- Kernel C: epilogue ----------------
__global__ void __launch_bounds__(256) epi_kernel(
    const float* __restrict__ xyz,
    const float* __restrict__ Wself, const float* __restrict__ W_lddt,
    const float* __restrict__ b_lddt,
    const float* __restrict__ g_state, const float* __restrict__ b_state,
    float* __restrict__ out)
{
    int w = threadIdx.x >> 5, lane = threadIdx.x & 31;
    int l = blockIdx.x * 8 + w;

    float acc = (g_m0p[(l * 2 + 0) * 32 + lane] + g_m0p[(l * 2 + 1) * 32 + lane]) * (1.f / KNN);
#pragma unroll
    for (int c = 0; c < 32; c++)
        acc = fmaf(g_node_feat[l * NL0 + c], __ldg(Wself + c * 32 + lane), acc);
    float mu = wsum(acc) * (1.f / 32.f);
    float d = acc - mu;
    float rs = rsqrtf(wsum(d * d) * (1.f / 32.f) + 1e-5f);
    float y = d * rs * g_state[lane] + b_state[lane];
    float tot = wsum(y * W_lddt[lane]);
    if (lane == 0)
        out[LQ * 9 + l] = 1.f / (1.f + expf(-(tot + b_lddt[0])));
    if (lane < 9) {
        int o = lane / 3, dd = lane % 3;
        float o1 = (g_o1p[(l * 2 + 0) * 12 + lane] + g_o1p[(l * 2 + 1) * 12 + lane]) * (1.f / KNN);
        float o1r1 = (g_o1p[(l * 2 + 0) * 12 + 3 + dd] + g_o1p[(l * 2 + 1) * 12 + 3 + dd]) * (1.f / KNN);
        float can = xyz[l * 9 + 3 + dd] + o1r1;
        float val = o1 + ((l == 0) ? 0.f : can);
        out[(l * 3 + o) * 3 + dd] = val;
    }
}

// ---------------- launch ----------------
extern "C" void kernel_launch(void* const* d_in, const int* in_sizes, int n_in,
                              void* d_out, int out_size)
{
    const float* xyz     = (const float*)d_in[0];
    const float* state   = (const float*)d_in[1];
    const float* msa     = (const float*)d_in[2];
    const float* pair    = (const float*)d_in[3];
    const float* seq1hot = (const float*)d_in[4];
    const float* g_msa   = (const float*)d_in[8];
    const float* b_msa   = (const float*)d_in[9];
    const float* g_pair  = (const float*)d_in[10];
    const float* b_pair  = (const float*)d_in[11];
    const float* g_state = (const float*)d_in[12];
    const float* b_state = (const float*)d_in[13];
    const float* W_x     = (const float*)d_in[14];
    const float* b_x     = (const float*)d_in[15];
    const float* g_node  = (const float*)d_in[16];
    const float* b_node  = (const float*)d_in[17];
    const float* W_e1    = (const float*)d_in[18];
    const float* b_e1    = (const float*)d_in[19];
    const float* g_ne1   = (const float*)d_in[20];
    const float* b_ne1   = (const float*)d_in[21];
    const float* W1      = (const float*)d_in[22];
    const float* b1      = (const float*)d_in[23];
    const float* W2      = (const float*)d_in[24];
    const float* b2      = (const float*)d_in[25];
    const float* Wv      = (const float*)d_in[26];
    const float* Wself   = (const float*)d_in[27];
    const float* W_lddt  = (const float*)d_in[28];
    const float* b_lddt  = (const float*)d_in[29];
    float* out = (float*)d_out;

    prep_kernel<<<LQ + 64 + 1, 256>>>(xyz, msa, seq1hot, state,
                                      g_msa, b_msa, g_state, b_state,
                                      W_x, b_x, g_node, b_node, W2, b2,
                                      g_pair, b_pair, W_e1, b_e1);
    pair_kernel<<<LQ * 2, 128, SMEMF * sizeof(float)>>>(
        xyz, pair, g_ne1, b_ne1, W1, b1, Wv);
    epi_kernel<<<LQ / 8, 256>>>(xyz, Wself, W_lddt, b_lddt, g_state, b_state, out);
}

// round 14
// speedup vs baseline: 1.2208x; 1.1908x over previous
#include <cuda_runtime.h>
#include <math.h>

#define LQ    512
#define KNN   64
#define DM    256
#define DP    128
#define DS    32
#define NL0   32
#define NRBF  36
#define MH    64
#define MOUT  38

// ---------------- scratch (static device arrays; no allocation) ----------------
__device__ float g_node_feat[LQ * NL0];
__device__ int   g_nbr[LQ * KNN];
__device__ __align__(16) float g_W2pad[MH * 48];
__device__ __align__(16) float g_b2pad[48];
__device__ __align__(16) float g_We1g[DP * 32];   // g_pair[c] * W_e1[c][j]
__device__ float g_S1[32];
__device__ float g_S2[32];
__device__ float g_m0[LQ * 32];       // full m0 column sums per residue
__device__ float g_o1p[LQ * 2 * 12];  // per-half out1 sums (9 used)

__device__ __forceinline__ float wsum(float v) {
#pragma unroll
    for (int o = 16; o; o >>= 1) v += __shfl_xor_sync(0xffffffffu, v, o);
    return v;
}
__device__ __forceinline__ void wsum2(float& a, float& b) {
#pragma unroll
    for (int o = 16; o; o >>= 1) {
        a += __shfl_xor_sync(0xffffffffu, a, o);
        b += __shfl_xor_sync(0xffffffffu, b, o);
    }
}

// ---- packed f32x2 helpers (lanewise exact fp32) ----
__device__ __forceinline__ unsigned long long pack2(float a) {
    unsigned long long r;
    asm("mov.b64 %0, {%1, %1};" : "=l"(r) : "f"(a));
    return r;
}
__device__ __forceinline__ unsigned long long pack2f(float lo, float hi) {
    unsigned long long r;
    asm("mov.b64 %0, {%1, %2};" : "=l"(r) : "f"(lo), "f"(hi));
    return r;
}
__device__ __forceinline__ void ffma2(unsigned long long& d, unsigned long long a, unsigned long long b) {
    asm("fma.rn.f32x2 %0, %1, %2, %0;" : "+l"(d) : "l"(a), "l"(b));
}
__device__ __forceinline__ float2 unpack2(unsigned long long v) {
    float x, y;
    asm("mov.b64 {%0, %1}, %2;" : "=f"(x), "=f"(y) : "l"(v));
    return make_float2(x, y);
}

// ---- warp-register bitonic helpers ----
__device__ __forceinline__ unsigned long long shflx64(unsigned long long v, int m) {
    unsigned lo = __shfl_xor_sync(0xffffffffu, (unsigned)v, m);
    unsigned hi = __shfl_xor_sync(0xffffffffu, (unsigned)(v >> 32), m);
    return ((unsigned long long)hi << 32) | lo;
}
__device__ __forceinline__ void ce64(unsigned long long& r, int j, bool up, int lane) {
    unsigned long long p = shflx64(r, j);
    bool lower = ((lane & j) == 0);
    bool kmin = (lower == up);
    bool pless = (p < r);
    r = (kmin == pless) ? p : r;
}
__device__ __forceinline__ void sort64(unsigned long long& r0, unsigned long long& r1,
                                       bool dir, int lane) {
#pragma unroll
    for (int k = 2; k <= 64; k <<= 1) {
#pragma unroll 6
        for (int j = k >> 1; j > 0; j >>= 1) {
            if (j == 32) {
                unsigned long long lo = (r0 < r1) ? r0 : r1;
                unsigned long long hi = (r0 < r1) ? r1 : r0;
                r0 = dir ? lo : hi; r1 = dir ? hi : lo;
            } else {
                bool up0, up1;
                if (k == 64)      { up0 = dir;  up1 = dir;  }
                else if (k == 32) { up0 = dir;  up1 = !dir; }
                else { bool u = (((lane & k) == 0) == dir); up0 = u; up1 = u; }
                ce64(r0, j, up0, lane);
                ce64(r1, j, up1, lane);
            }
        }
    }
}
__device__ __forceinline__ void merge64(unsigned long long& r0, unsigned long long& r1,
                                        bool dir, int lane) {
    {
        unsigned long long lo = (r0 < r1) ? r0 : r1;
        unsigned long long hi = (r0 < r1) ? r1 : r0;
        r0 = dir ? lo : hi; r1 = dir ? hi : lo;
    }
#pragma unroll
    for (int j = 16; j > 0; j >>= 1) {
        ce64(r0, j, dir, lane);
        ce64(r1, j, dir, lane);
    }
}

// ---------------- Kernel A: node features (0..63) + weight prep (64) + topk (65..576) ----------------
__global__ void __launch_bounds__(256) prep_kernel(
    const float* __restrict__ xyz,
    const float* __restrict__ msa, const float* __restrict__ seq1hot,
    const float* __restrict__ state,
    const float* __restrict__ g_msa, const float* __restrict__ b_msa,
    const float* __restrict__ g_state, const float* __restrict__ b_state,
    const float* __restrict__ W_x, const float* __restrict__ b_x,
    const float* __restrict__ g_node, const float* __restrict__ b_node,
    const float* __restrict__ W2, const float* __restrict__ b2,
    const float* __restrict__ g_pair, const float* __restrict__ b_pair,
    const float* __restrict__ W_e1, const float* __restrict__ b_e1)
{
    __shared__ __align__(16) float smem_f[3072];
    int tid = threadIdx.x;
    int w = tid >> 5, lane = tid & 31;

    if (blockIdx.x < 64) {
        int l = blockIdx.x * 8 + w;
        float* sx = smem_f + w * 312;

        float m[8]; float s0 = 0.f;
#pragma unroll
        for (int q = 0; q < 8; q++) { m[q] = msa[l * DM + lane + 32 * q]; s0 += m[q]; }
        float mu = wsum(s0) * (1.f / DM);
        float v0 = 0.f;
#pragma unroll
        for (int q = 0; q < 8; q++) { float d = m[q] - mu; v0 += d * d; }
        float rs = rsqrtf(wsum(v0) * (1.f / DM) + 1e-5f);
#pragma unroll
        for (int q = 0; q < 8; q++) {
            int c = lane + 32 * q;
            sx[c] = (m[q] - mu) * rs * g_msa[c] + b_msa[c];
        }
        if (lane < 21) sx[DM + lane] = seq1hot[l * 21 + lane];
        {
            float st = state[l * DS + lane];
            float mu2 = wsum(st) * (1.f / DS);
            float d = st - mu2;
            float rs2 = rsqrtf(wsum(d * d) * (1.f / DS) + 1e-5f);
            sx[DM + 21 + lane] = d * rs2 * g_state[lane] + b_state[lane];
        }
        __syncwarp();

        float a0 = b_x[lane], a1 = 0.f, a2 = 0.f, a3 = 0.f;
        for (int c = 0; c < 308; c += 4) {
            a0 = fmaf(sx[c + 0], __ldg(W_x + (c + 0) * NL0 + lane), a0);
            a1 = fmaf(sx[c + 1], __ldg(W_x + (c + 1) * NL0 + lane), a1);
            a2 = fmaf(sx[c + 2], __ldg(W_x + (c + 2) * NL0 + lane), a2);
            a3 = fmaf(sx[c + 3], __ldg(W_x + (c + 3) * NL0 + lane), a3);
        }
        float acc = (a0 + a1) + (a2 + a3) + sx[308] * __ldg(W_x + 308 * NL0 + lane);

        float mu3 = wsum(acc) * (1.f / NL0);
        float d3 = acc - mu3;
        float rs3 = rsqrtf(wsum(d3 * d3) * (1.f / NL0) + 1e-5f);
        g_node_feat[l * NL0 + lane] = d3 * rs3 * g_node[lane] + b_node[lane];
    } else if (blockIdx.x == 64) {
        for (int i = tid; i < MH * 48; i += 256) {
            int h = i / 48, c = i - h * 48;
            g_W2pad[i] = (c < MOUT) ? W2[h * MOUT + c] : 0.f;
        }
        if (tid < 48) g_b2pad[tid] = (tid < MOUT) ? b2[tid] : 0.f;
        for (int i = tid; i < DP * 32; i += 256) {
            int c = i >> 5;
            g_We1g[i] = g_pair[c] * W_e1[i];
        }
        if (tid < 32) {
            float s1 = 0.f, s2 = 0.f;
            for (int c = 0; c < DP; c++) {
                float wv = W_e1[c * 32 + tid];
                s1 = fmaf(g_pair[c], wv, s1);
                s2 = fmaf(b_pair[c], wv, s2);
            }
            g_S1[tid] = s1;
            g_S2[tid] = s2 + b_e1[tid];
        }
    } else {
        int i = blockIdx.x - 65;
        float* sca = smem_f;
        unsigned long long* ks = (unsigned long long*)(smem_f + 1536);

        for (int j = tid; j < LQ; j += 256) {
            sca[j * 3 + 0] = xyz[j * 9 + 3];
            sca[j * 3 + 1] = xyz[j * 9 + 4];
            sca[j * 3 + 2] = xyz[j * 9 + 5];
        }
        __syncthreads();
        float cx = sca[i * 3 + 0], cy = sca[i * 3 + 1], cz = sca[i * 3 + 2];

        int j0 = w * 64 + lane;
        int j1 = j0 + 32;
        float dx0 = sca[j0 * 3 + 0] - cx, dy0 = sca[j0 * 3 + 1] - cy, dz0 = sca[j0 * 3 + 2] - cz;
        float d20 = dx0 * dx0 + dy0 * dy0 + dz0 * dz0;
        if (j0 == i) d20 += 1e9f;
        float dx1 = sca[j1 * 3 + 0] - cx, dy1 = sca[j1 * 3 + 1] - cy, dz1 = sca[j1 * 3 + 2] - cz;
        float d21 = dx1 * dx1 + dy1 * dy1 + dz1 * dz1;
        if (j1 == i) d21 += 1e9f;
        unsigned long long k0 = (((unsigned long long)__float_as_uint(d20)) << 32) | (unsigned)j0;
        unsigned long long k1 = (((unsigned long long)__float_as_uint(d21)) << 32) | (unsigned)j1;

        sort64(k0, k1, (w & 1) == 0, lane);
        ks[w * 64 + lane] = k0;
        ks[w * 64 + 32 + lane] = k1;
        __syncthreads();

        if (w < 4) {
            int ba = (2 * w) * 64, bb = (2 * w + 1) * 64;
            unsigned long long a0 = ks[ba + lane], a1 = ks[ba + 32 + lane];
            unsigned long long c0 = ks[bb + lane], c1 = ks[bb + 32 + lane];
            k0 = (a0 < c0) ? a0 : c0;
            k1 = (a1 < c1) ? a1 : c1;
            merge64(k0, k1, (w & 1) == 0, lane);
            ks[512 + w * 64 + lane] = k0;
            ks[512 + w * 64 + 32 + lane] = k1;
        }
        __syncthreads();

        if (w < 2) {
            int ba = 512 + (2 * w) * 64, bb = 512 + (2 * w + 1) * 64;
            unsigned long long a0 = ks[ba + lane], a1 = ks[ba + 32 + lane];
            unsigned long long c0 = ks[bb + lane], c1 = ks[bb + 32 + lane];
            k0 = (a0 < c0) ? a0 : c0;
            k1 = (a1 < c1) ? a1 : c1;
            merge64(k0, k1, (w & 1) == 0, lane);
            ks[w * 64 + lane] = k0;
            ks[w * 64 + 32 + lane] = k1;
        }
        __syncthreads();

        if (w == 0) {
            unsigned long long a0 = ks[lane],      a1 = ks[32 + lane];
            unsigned long long c0 = ks[64 + lane], c1 = ks[96 + lane];
            k0 = (a0 < c0) ? a0 : c0;
            k1 = (a1 < c1) ? a1 : c1;
            g_nbr[i * KNN + lane]      = (int)(k0 & 0xffffffffull);
            g_nbr[i * KNN + 32 + lane] = (int)(k1 & 0xffffffffull);
        }
    }
}

// ---------------- Kernel B: full-residue (64 pairs) edge MLP, 8 warps ----------------
// smem layout (floats), P=64 pairs, stride 65
#define OFF_INVT   0        // 103*65 = 6695
#define OFF_BUF    6695     // 64*65 = 4160 (pn chunk; later hT 64x65)
#define OFF_GVGD   10855    // 64*6 = 384
#define OFF_MURS   11239    // 128 (mu,rs per pair)
#define OFF_HBASE  11367    // 64
#define OFF_GNE1   11431    // 32
#define OFF_BNE1   11463    // 32
#define OFF_NODEI  11495    // 32
#define OFF_CA     11527    // 4
#define OFF_WV     11531    // 12
#define OFF_NBR    11543    // 64 ints
#define OFF_RELHAT 11607    // 64*3 = 192
#define SMEMF      11799

__global__ void __launch_bounds__(256, 4) pair_kernel(
    const float* __restrict__ xyz, const float* __restrict__ pair,
    const float* __restrict__ g_ne1, const float* __restrict__ b_ne1,
    const float* __restrict__ W1, const float* __restrict__ b1,
    const float* __restrict__ Wv)
{
    extern __shared__ float s[];
    int l = blockIdx.x;
    int tid = threadIdx.x;
    int w = tid >> 5, lane = tid & 31;

    // ---- front-batched loads: neighbors + all 64 pair rows (8 per warp) ----
    int jj[8];
#pragma unroll
    for (int t = 0; t < 8; t++)
        jj[t] = __ldg(g_nbr + l * KNN + t * 8 + w);
    float A0[8], A1[8], A2[8], A3[8];
#pragma unroll
    for (int t = 0; t < 8; t++) {
        const float* prow = pair + ((size_t)l * LQ + jj[t]) * DP;
        A0[t] = __ldcs(prow + lane);
        A1[t] = __ldcs(prow + lane + 32);
        A2[t] = __ldcs(prow + lane + 64);
        A3[t] = __ldcs(prow + lane + 96);
    }

    // ---- stage small vectors ----
    if (tid < 32) {
        s[OFF_GNE1 + tid] = g_ne1[tid];
        s[OFF_BNE1 + tid] = b_ne1[tid];
        s[OFF_NODEI + tid] = g_node_feat[l * NL0 + tid];
    }
    if (tid < 64) ((int*)(s + OFF_NBR))[tid] = g_nbr[l * KNN + tid];
    if (tid < 3) s[OFF_CA + tid] = xyz[l * 9 + 3 + tid];
    if (tid < 9) s[OFF_WV + tid] = Wv[tid];
    __syncthreads();

    // ---- hbase (warps 0,1) ----
    if (tid < 64) {
        float a = b1[tid];
#pragma unroll
        for (int c = 0; c < 32; c++)
            a = fmaf(s[OFF_NODEI + c], __ldg(W1 + c * 64 + tid), a);
        s[OFF_HBASE + tid] = a;
    }

    // ---- P1: stats + stage rows 0..63 of pn + geometry ----
    float ca0 = s[OFF_CA + 0], ca1 = s[OFF_CA + 1], ca2 = s[OFF_CA + 2];
#pragma unroll
    for (int t = 0; t < 8; t++) {
        int p = t * 8 + w;
        int j = jj[t];
        float a0 = A0[t], a1 = A1[t], a2 = A2[t], a3 = A3[t];
        float sum = a0 + a1 + a2 + a3;
        float ssq = a0 * a0 + a1 * a1 + a2 * a2 + a3 * a3;
        wsum2(sum, ssq);
        float mu = sum * (1.f / DP);
        float var = ssq * (1.f / DP) - mu * mu;
        float rs = rsqrtf(var + 1e-5f);
        s[OFF_BUF + lane * 65 + p] = a0;
        s[OFF_BUF + (lane + 32) * 65 + p] = a1;
        if (lane == 0) { s[OFF_MURS + 2 * p] = mu; s[OFF_MURS + 2 * p + 1] = rs; }

        s[OFF_INVT + lane * 65 + p] = g_node_feat[j * NL0 + lane];
        float cj0 = xyz[j * 9 + 3], cj1 = xyz[j * 9 + 4], cj2 = xyz[j * 9 + 5];
        float r0 = cj0 - ca0, r1 = cj1 - ca1, r2 = cj2 - ca2;
        float r = sqrtf(r0 * r0 + r1 * r1 + r2 * r2 + 1e-8f);
        {
            float c1 = (20.f / 35.f) * lane;
            float u = (r - c1) * 1.8f;
            s[OFF_INVT + (64 + lane) * 65 + p] = __expf(-u * u);
            if (lane < 4) {
                float c2 = (20.f / 35.f) * (lane + 32);
                float u2 = (r - c2) * 1.8f;
                s[OFF_INVT + (96 + lane) * 65 + p] = __expf(-u2 * u2);
            }
        }
        if (lane < 3) {
            float rel = (lane == 0) ? r0 : ((lane == 1) ? r1 : r2);
            s[OFF_RELHAT + p * 3 + lane] = rel / r;
            float b0 = xyz[j * 9 + lane * 3 + 0] - cj0;
            float b1v = xyz[j * 9 + lane * 3 + 1] - cj1;
            float b2v = xyz[j * 9 + lane * 3 + 2] - cj2;
            s[OFF_INVT + (100 + lane) * 65 + p] = sqrtf(b0 * b0 + b1v * b1v + b2v * b2v + 1e-8f);
        }
    }
    __syncthreads();

    // rows handled per lane: r0 = lane, r1 = lane + 32 (packed .lo/.hi)
    // ---- GEMM1-A (k=0..63): col slice w*4, accs 4 x f32x2 ----
    unsigned long long acc1[4];
    {
        int col0 = w * 4;
        acc1[0] = acc1[1] = acc1[2] = acc1[3] = 0ull;
#pragma unroll 2
        for (int c = 0; c < 64; c++) {
            unsigned long long ap = pack2f(s[OFF_BUF + c * 65 + lane],
                                           s[OFF_BUF + c * 65 + lane + 32]);
            float4 wv = __ldg((const float4*)(g_We1g + c * 32 + col0));
            ffma2(acc1[0], ap, pack2(wv.x)); ffma2(acc1[1], ap, pack2(wv.y));
            ffma2(acc1[2], ap, pack2(wv.z)); ffma2(acc1[3], ap, pack2(wv.w));
        }
    }
    __syncthreads();

    // ---- P2: stage rows 64..127 ----
#pragma unroll
    for (int t = 0; t < 8; t++) {
        int p = t * 8 + w;
        s[OFF_BUF + lane * 65 + p] = A2[t];
        s[OFF_BUF + (lane + 32) * 65 + p] = A3[t];
    }
    __syncthreads();

    // ---- GEMM1-B (k=64..127) + LN-fold -> E_pre rows 32..63 of INVT ----
    {
        int col0 = w * 4;
#pragma unroll 2
        for (int c = 0; c < 64; c++) {
            unsigned long long ap = pack2f(s[OFF_BUF + c * 65 + lane],
                                           s[OFF_BUF + c * 65 + lane + 32]);
            float4 wv = __ldg((const float4*)(g_We1g + (64 + c) * 32 + col0));
            ffma2(acc1[0], ap, pack2(wv.x)); ffma2(acc1[1], ap, pack2(wv.y));
            ffma2(acc1[2], ap, pack2(wv.z)); ffma2(acc1[3], ap, pack2(wv.w));
        }
        float mu0 = s[OFF_MURS + 2 * lane],        rs0 = s[OFF_MURS + 2 * lane + 1];
        float mu1 = s[OFF_MURS + 2 * (lane + 32)], rs1 = s[OFF_MURS + 2 * (lane + 32) + 1];
#pragma unroll
        for (int q = 0; q < 4; q++) {
            float2 v = unpack2(acc1[q]);
            int c0 = col0 + q;
            float s1v = __ldg(g_S1 + c0), s2v = __ldg(g_S2 + c0);
            s[OFF_INVT + (32 + c0) * 65 + lane]      = rs0 * v.x - rs0 * mu0 * s1v + s2v;
            s[OFF_INVT + (32 + c0) * 65 + lane + 32] = rs1 * v.y - rs1 * mu1 * s1v + s2v;
        }
    }
    __syncthreads();

    // ---- LN over e_pre (32) per pair ----
#pragma unroll 2
    for (int t = 0; t < 8; t++) {
        int p = t * 8 + w;
        float x = s[OFF_INVT + (32 + lane) * 65 + p];
        float sum = x, ssq = x * x;
        wsum2(sum, ssq);
        float mu = sum * (1.f / 32.f);
        float var = ssq * (1.f / 32.f) - mu * mu;
        float rs = rsqrtf(var + 1e-5f);
        s[OFF_INVT + (32 + lane) * 65 + p] = (x - mu) * rs * s[OFF_GNE1 + lane] + s[OFF_BNE1 + lane];
    }
    __syncthreads();

    // ---- GEMM2: col slice w*8, 2 rows/lane packed -> H into BUF ----
    {
        int col0 = w * 8;
        const float* w1base = W1 + 32 * 64 + col0;
        unsigned long long acc[8];
#pragma unroll
        for (int q = 0; q < 8; q++) acc[q] = pack2(s[OFF_HBASE + col0 + q]);
#pragma unroll 2
        for (int cc = 0; cc < 103; cc++) {
            unsigned long long ap = pack2f(s[OFF_INVT + cc * 65 + lane],
                                           s[OFF_INVT + cc * 65 + lane + 32]);
            float4 w0 = __ldg((const float4*)(w1base + cc * 64));
            float4 w1v = __ldg((const float4*)(w1base + cc * 64 + 4));
            ffma2(acc[0], ap, pack2(w0.x));  ffma2(acc[1], ap, pack2(w0.y));
            ffma2(acc[2], ap, pack2(w0.z));  ffma2(acc[3], ap, pack2(w0.w));
            ffma2(acc[4], ap, pack2(w1v.x)); ffma2(acc[5], ap, pack2(w1v.y));
            ffma2(acc[6], ap, pack2(w1v.z)); ffma2(acc[7], ap, pack2(w1v.w));
        }
#pragma unroll
        for (int q = 0; q < 8; q++) {
            float2 v = unpack2(acc[q]);
            s[OFF_BUF + (col0 + q) * 65 + lane]      = fmaxf(v.x, 0.f);
            s[OFF_BUF + (col0 + q) * 65 + lane + 32] = fmaxf(v.y, 0.f);
        }
    }
    __syncthreads();

    // ---- GEMM3: col slice w*6 (48 cols / 8 warps); m0 full sums + gv/gd ----
    {
        int col0 = w * 6;
        unsigned long long acc[6];
#pragma unroll
        for (int q = 0; q < 6; q++) acc[q] = pack2(g_b2pad[col0 + q]);
#pragma unroll 2
        for (int h = 0; h < 64; h++) {
            unsigned long long ap = pack2f(s[OFF_BUF + h * 65 + lane],
                                           s[OFF_BUF + h * 65 + lane + 32]);
            float2 w0 = __ldg((const float2*)(g_W2pad + h * 48 + col0));
            float2 w1v = __ldg((const float2*)(g_W2pad + h * 48 + col0 + 2));
            float2 w2v = __ldg((const float2*)(g_W2pad + h * 48 + col0 + 4));
            ffma2(acc[0], ap, pack2(w0.x));  ffma2(acc[1], ap, pack2(w0.y));
            ffma2(acc[2], ap, pack2(w1v.x)); ffma2(acc[3], ap, pack2(w1v.y));
            ffma2(acc[4], ap, pack2(w2v.x)); ffma2(acc[5], ap, pack2(w2v.y));
        }
#pragma unroll
        for (int q = 0; q < 6; q++) {
            int cg = col0 + q;
            float2 v = unpack2(acc[q]);
            if (cg < 32) {
                float red = wsum(v.x + v.y);          // sum over all 64 pairs
                if (lane == 0) g_m0[l * 32 + cg] = red;
            } else if (cg < 38) {
                s[OFF_GVGD + lane * 6 + (cg - 32)]        = v.x;
                s[OFF_GVGD + (lane + 32) * 6 + (cg - 32)] = v.y;
            }
        }
    }
    __syncthreads();

    // ---- out1 half-sums (warps 0,1: 32 pairs each) ----
    if (tid < 64) {
        int p = lane + w * 32;
        int j = ((const int*)(s + OFF_NBR))[p];
        float cj0 = xyz[j * 9 + 3], cj1 = xyz[j * 9 + 4], cj2 = xyz[j * 9 + 5];
        float v1[3][3];
#pragma unroll
        for (int c = 0; c < 3; c++) {
            v1[c][0] = xyz[j * 9 + c * 3 + 0] - cj0;
            v1[c][1] = xyz[j * 9 + c * 3 + 1] - cj1;
            v1[c][2] = xyz[j * 9 + c * 3 + 2] - cj2;
        }
        float rh[3] = { s[OFF_RELHAT + p * 3 + 0], s[OFF_RELHAT + p * 3 + 1], s[OFF_RELHAT + p * 3 + 2] };
#pragma unroll
        for (int o = 0; o < 3; o++) {
            float gvv = s[OFF_GVGD + p * 6 + o];
            float gdd = s[OFF_GVGD + p * 6 + 3 + o];
            float wv0 = s[OFF_WV + o * 3 + 0], wv1 = s[OFF_WV + o * 3 + 1], wv2 = s[OFF_WV + o * 3 + 2];
#pragma unroll
            for (int d = 0; d < 3; d++) {
                float vm = wv0 * v1[0][d] + wv1 * v1[1][d] + wv2 * v1[2][d];
                float contrib = gvv * vm + gdd * rh[d];
                float red = wsum(contrib);
                if (lane == 0) g_o1p[(l * 2 + w) * 12 + o * 3 + d] = red;
            }
        }
    }
}

// ---------------- Kernel C: epilogue ----------------
__global__ void __launch_bounds__(256) epi_kernel(
    const float* __restrict__ xyz,
    const float* __restrict__ Wself, const float* __restrict__ W_lddt,
    const float* __restrict__ b_lddt,
    const float* __restrict__ g_state, const float* __restrict__ b_state,
    float* __restrict__ out)
{
    int w = threadIdx.x >> 5, lane = threadIdx.x & 31;
    int l = blockIdx.x * 8 + w;

    float acc = g_m0[l * 32 + lane] * (1.f / KNN);
#pragma unroll
    for (int c = 0; c < 32; c++)
        acc = fmaf(g_node_feat[l * NL0 + c], __ldg(Wself + c * 32 + lane), acc);
    float mu = wsum(acc) * (1.f / 32.f);
    float d = acc - mu;
    float rs = rsqrtf(wsum(d * d) * (1.f / 32.f) + 1e-5f);
    float y = d * rs * g_state[lane] + b_state[lane];
    float tot = wsum(y * W_lddt[lane]);
    if (lane == 0)
        out[LQ * 9 + l] = 1.f / (1.f + expf(-(tot + b_lddt[0])));
    if (lane < 9) {
        int o = lane / 3, dd = lane % 3;
        float o1 = (g_o1p[(l * 2 + 0) * 12 + lane] + g_o1p[(l * 2 + 1) * 12 + lane]) * (1.f / KNN);
        float o1r1 = (g_o1p[(l * 2 + 0) * 12 + 3 + dd] + g_o1p[(l * 2 + 1) * 12 + 3 + dd]) * (1.f / KNN);
        float can = xyz[l * 9 + 3 + dd] + o1r1;
        float val = o1 + ((l == 0) ? 0.f : can);
        out[(l * 3 + o) * 3 + dd] = val;
    }
}

// ---------------- launch ----------------
extern "C" void kernel_launch(void* const* d_in, const int* in_sizes, int n_in,
                              void* d_out, int out_size)
{
    const float* xyz     = (const float*)d_in[0];
    const float* state   = (const float*)d_in[1];
    const float* msa     = (const float*)d_in[2];
    const float* pair    = (const float*)d_in[3];
    const float* seq1hot = (const float*)d_in[4];
    const float* g_msa   = (const float*)d_in[8];
    const float* b_msa   = (const float*)d_in[9];
    const float* g_pair  = (const float*)d_in[10];
    const float* b_pair  = (const float*)d_in[11];
    const float* g_state = (const float*)d_in[12];
    const float* b_state = (const float*)d_in[13];
    const float* W_x     = (const float*)d_in[14];
    const float* b_x     = (const float*)d_in[15];
    const float* g_node  = (const float*)d_in[16];
    const float* b_node  = (const float*)d_in[17];
    const float* W_e1    = (const float*)d_in[18];
    const float* b_e1    = (const float*)d_in[19];
    const float* g_ne1   = (const float*)d_in[20];
    const float* b_ne1   = (const float*)d_in[21];
    const float* W1      = (const float*)d_in[22];
    const float* b1      = (const float*)d_in[23];
    const float* W2      = (const float*)d_in[24];
    const float* b2      = (const float*)d_in[25];
    const float* Wv      = (const float*)d_in[26];
    const float* Wself   = (const float*)d_in[27];
    const float* W_lddt  = (const float*)d_in[28];
    const float* b_lddt  = (const float*)d_in[29];
    float* out = (float*)d_out;

    cudaFuncSetAttribute(pair_kernel, cudaFuncAttributeMaxDynamicSharedMemorySize,
                         SMEMF * (int)sizeof(float));

    prep_kernel<<<LQ + 64 + 1, 256>>>(xyz, msa, seq1hot, state,
                                      g_msa, b_msa, g_state, b_state,
                                      W_x, b_x, g_node, b_node, W2, b2,
                                      g_pair, b_pair, W_e1, b_e1);
    pair_kernel<<<LQ, 256, SMEMF * sizeof(float)>>>(
        xyz, pair, g_ne1, b_ne1, W1, b1, Wv);
    epi_kernel<<<LQ / 8, 256>>>(xyz, Wself, W_lddt, b_lddt, g_state, b_state, out);
}